// round 7
// baseline (speedup 1.0000x reference)
#include <cuda_runtime.h>
#include <cuda_bf16.h>

// out[0,d,h,w,c] = in[0, z[d], row[h], col[w], 0]
// in (1,128,128,128,32) f32; z/row/col (64,) i32; out (1,64,64,64,32) f32.
//
// Two-kernel split to separate DRAM reads from DRAM writes in time
// (avoid HBM read/write bus turnaround interference):
//   A: gather 64^3 scalars -> compact 1MB __device__ buffer (read phase)
//   B: broadcast compact buffer (L2-resident) -> 32MB output (pure write phase)

__device__ float g_compact[64 * 64 * 64];   // 1 MiB scratch (static, allowed)

__global__ __launch_bounds__(256) void gather_kernel(
    const float* __restrict__ in,
    const int* __restrict__ zi,
    const int* __restrict__ ri,
    const int* __restrict__ ci)
{
    int pos = blockIdx.x * 256 + threadIdx.x;    // 0 .. 64^3-1
    int w = pos & 63;
    int h = (pos >> 6) & 63;
    int d = pos >> 12;

    int src = (__ldg(zi + d) << 7) + __ldg(ri + h);   // z*128 + row
    src = ((src << 7) + __ldg(ci + w)) << 5;          // (*128 + col)*32

    g_compact[pos] = __ldg(in + src);
}

__global__ __launch_bounds__(256) void broadcast_kernel(float4* __restrict__ out)
{
    int gid = blockIdx.x * blockDim.x + threadIdx.x;  // 0 .. 64^3*8-1
    float v = __ldg(&g_compact[gid >> 3]);            // L1/L2 hit, 8-way broadcast
    out[gid] = make_float4(v, v, v, v);
}

extern "C" void kernel_launch(void* const* d_in, const int* in_sizes, int n_in,
                              void* d_out, int out_size)
{
    const float* in  = (const float*)d_in[0];
    const int*   zi  = (const int*)d_in[1];
    const int*   ri  = (const int*)d_in[2];
    const int*   ci  = (const int*)d_in[3];
    float4*      out = (float4*)d_out;

    // A: 64^3 = 262144 gathers, 1024 blocks x 256
    gather_kernel<<<1024, 256>>>(in, zi, ri, ci);
    // B: 64^3*8 = 2097152 float4 stores, 8192 blocks x 256
    broadcast_kernel<<<8192, 256>>>(out);
}

// round 8
// speedup vs baseline: 1.2135x; 1.2135x over previous
#include <cuda_runtime.h>
#include <cuda_bf16.h>
#include <cstdint>

// out[0,d,h,w,c] = in[0, z[d], row[h], col[w], 0]
// in (1,128,128,128,32) f32; z/row/col (64,) i32; out (1,64,64,64,32) f32.
//
// Warp-tile kernel: each warp owns 32 consecutive positions.
//   1) each lane gathers its position's scalar (32 independent LDGs, MLP=32)
//   2) 4 rounds of SHFL + 256-bit store: warp writes its 4KB output tile
//      in 4 STG.256 instructions (1KB contiguous per instruction).

__global__ __launch_bounds__(256) void sdown3d_kernel(
    const float* __restrict__ in,
    const int* __restrict__ zi,
    const int* __restrict__ ri,
    const int* __restrict__ ci,
    float* __restrict__ out)
{
    const int lane = threadIdx.x & 31;
    const int warp = threadIdx.x >> 5;
    const int warpBase = (blockIdx.x * 8 + warp) * 32;   // first position of this warp
    const int pos = warpBase + lane;

    const int w = pos & 63;
    const int h = (pos >> 6) & 63;
    const int d = pos >> 12;

    // independent gather per lane
    int src = (__ldg(zi + d) << 7) + __ldg(ri + h);     // z*128 + row
    src = ((src << 7) + __ldg(ci + w)) << 5;            // (*128 + col)*32
    const float v = __ldg(in + src);

    // warp's output tile: 32 positions * 128B = 4KB, contiguous
    float* ob = out + (size_t)warpBase * 32;

    #pragma unroll
    for (int i = 0; i < 4; i++) {
        // 32B chunk index within tile = i*32 + lane; position = chunk>>2
        const float s = __shfl_sync(0xffffffffu, v, i * 8 + (lane >> 2));
        float* p = ob + (size_t)(i * 32 + lane) * 8;
        asm volatile(
            "st.global.v8.f32 [%0], {%1,%2,%3,%4,%5,%6,%7,%8};"
            :: "l"(p), "f"(s), "f"(s), "f"(s), "f"(s),
                       "f"(s), "f"(s), "f"(s), "f"(s)
            : "memory");
    }
}

extern "C" void kernel_launch(void* const* d_in, const int* in_sizes, int n_in,
                              void* d_out, int out_size)
{
    const float* in  = (const float*)d_in[0];
    const int*   zi  = (const int*)d_in[1];
    const int*   ri  = (const int*)d_in[2];
    const int*   ci  = (const int*)d_in[3];
    float*       out = (float*)d_out;

    // 64^3 = 262144 positions; 32 per warp, 8 warps per block -> 1024 blocks
    sdown3d_kernel<<<1024, 256>>>(in, zi, ri, ci, out);
}